// round 16
// baseline (speedup 1.0000x reference)
#include <cuda_runtime.h>
#include <cuda_bf16.h>
#include <cuda_fp16.h>
#include <math.h>
#include <stdint.h>

// Problem constants
#define NROWS 16384
#define DIN   1024
#define DEMB  256
#define KCB   1024
#define ALPHA 0.01f
#define EPSV  1e-5f
#define MARGIN 4.0f

// Output layout (float32, tuple order concatenated)
#define OFF_X        ((size_t)0)
#define OFF_CODES    ((size_t)16777216)
#define OFF_EMB      ((size_t)16793600)
#define OFF_COMMIT   ((size_t)16793601)
#define OFF_ENT      ((size_t)16793602)
#define OFF_EMA_VECS ((size_t)16793603)
#define OFF_EMA_SIZE ((size_t)17055747)
#define OFF_WEIGHT   ((size_t)17056771)

// ---------------------------------------------------------------------------
// Scratch (device globals; no allocations allowed)
__device__ float g_z[NROWS * DEMB];
__device__ float g_sqr[KCB];
__device__ float g_upd[KCB * DEMB];
__device__ float g_cnt[KCB];
__device__ float g_loss;
__device__ float g_size[KCB];
__device__ float g_Y[KCB * DIN];
__device__ __half g_dist[NROWS * KCB];        // 32 MB approx distances (fp16)
__device__ __nv_bfloat16 g_zh[NROWS * DEMB];  // bf16 z for cov
__device__ __nv_bfloat16 g_cbh[KCB * DEMB];   // bf16 codebook for cov
// fp16 hi/lo operand splits
__device__ __half g_wsh[DEMB * DIN],  g_wsl[DEMB * DIN];      // W_send^T [256,1024]
__device__ __half g_wrh[DIN * DEMB],  g_wrl[DIN * DEMB];      // W_recv^T [1024,256]
__device__ __half g_cbh16[KCB * DEMB], g_cbl16[KCB * DEMB];   // codebook

// ---------------------------------------------------------------------------
__device__ __forceinline__ uint32_t smem_u32(const void* p) {
    uint32_t a;
    asm("{ .reg .u64 t; cvta.to.shared.u64 t, %1; cvt.u32.u64 %0, t; }" : "=r"(a) : "l"(p));
    return a;
}
__device__ __forceinline__ void ldsm4(uint32_t* r, uint32_t addr) {
    asm volatile("ldmatrix.sync.aligned.m8n8.x4.shared.b16 {%0,%1,%2,%3}, [%4];"
                 : "=r"(r[0]), "=r"(r[1]), "=r"(r[2]), "=r"(r[3]) : "r"(addr));
}
__device__ __forceinline__ void mma_f16(float* c, const uint32_t* a, const uint32_t* b) {
    asm volatile("mma.sync.aligned.m16n8k16.row.col.f32.f16.f16.f32 "
                 "{%0,%1,%2,%3}, {%4,%5,%6,%7}, {%8,%9}, {%0,%1,%2,%3};"
                 : "+f"(c[0]), "+f"(c[1]), "+f"(c[2]), "+f"(c[3])
                 : "r"(a[0]), "r"(a[1]), "r"(a[2]), "r"(a[3]), "r"(b[0]), "r"(b[1]));
}
__device__ __forceinline__ void mma_bf16(float* c, const uint32_t* a, const uint32_t* b) {
    asm volatile("mma.sync.aligned.m16n8k16.row.col.f32.bf16.bf16.f32 "
                 "{%0,%1,%2,%3}, {%4,%5,%6,%7}, {%8,%9}, {%0,%1,%2,%3};"
                 : "+f"(c[0]), "+f"(c[1]), "+f"(c[2]), "+f"(c[3])
                 : "r"(a[0]), "r"(a[1]), "r"(a[2]), "r"(a[3]), "r"(b[0]), "r"(b[1]));
}
#define CP16(sm, gp) asm volatile("cp.async.ca.shared.global [%0], [%1], 16;" :: "r"(sm), "l"(gp))
#define CPCOMMIT()   asm volatile("cp.async.commit_group;" ::: "memory")
#define CPWAIT0()    asm volatile("cp.async.wait_group 0;" ::: "memory")
#define CPWAIT1()    asm volatile("cp.async.wait_group 1;" ::: "memory")

// smem tile geometry (validated R8-R15)
#define HSTRIDE 40
#define HARR (128 * HSTRIDE)
#define HSTAGE (4 * HARR)
#define HSMEM_BYTES (2 * HSTAGE * 2)  // 81920

// ===========================================================================
// z GEMM (fp16x3) with fused A split (fp32 LDG -> in-register hi/lo -> STS).
// rybase: row-tile offset for the two-half pipeline.
__device__ __forceinline__ void zb_loads(uint32_t sbase, int buf,
    const __half* __restrict__ Bh, const __half* __restrict__ Bl,
    int col0, int kdim, int kc, int tid)
{
    #pragma unroll
    for (int i = 0; i < 2; i++) {
        int seg = tid + i * 256;
        int rr = seg >> 2, cc = (seg & 3) * 8;
        uint32_t so = sbase + (uint32_t)(buf * HSTAGE + rr * HSTRIDE + cc) * 2u;
        CP16(so + 2u * HARR * 2u, Bh + (size_t)(col0 + rr) * kdim + kc + cc);
        CP16(so + 3u * HARR * 2u, Bl + (size_t)(col0 + rr) * kdim + kc + cc);
    }
    CPCOMMIT();
}

__global__ __launch_bounds__(256, 2) void k_zgemm(
    const float* __restrict__ A,
    const __half* __restrict__ Bh, const __half* __restrict__ Bl,
    const float* __restrict__ bias, float* __restrict__ C,
    __nv_bfloat16* __restrict__ Chi, int ldc, int kdim, int rybase)
{
    extern __shared__ __half hsm[];
    const int tid = threadIdx.x, lane = tid & 31, wid = tid >> 5;
    const int warp_m = wid & 3, warp_n = wid >> 2;
    const int row0 = (blockIdx.y + rybase) * 128, col0 = blockIdx.x * 128;
    const uint32_t sbase = smem_u32(hsm);
    const int quad = lane >> 3;

    const int arr = tid >> 1;
    const int acb = (tid & 1) * 16;

    float areg[16];
    float acc[2][8][4];
    #pragma unroll
    for (int a = 0; a < 2; a++)
        #pragma unroll
        for (int b = 0; b < 8; b++)
            #pragma unroll
            for (int c = 0; c < 4; c++) acc[a][b][c] = 0.0f;

    const int nch = kdim >> 5;
    const float* Abase = A + (size_t)(row0 + arr) * kdim + acb;
    #define LDGA(kc) do { \
        const float* _p = Abase + (kc); \
        *reinterpret_cast<float4*>(areg + 0)  = *reinterpret_cast<const float4*>(_p); \
        *reinterpret_cast<float4*>(areg + 4)  = *reinterpret_cast<const float4*>(_p + 4); \
        *reinterpret_cast<float4*>(areg + 8)  = *reinterpret_cast<const float4*>(_p + 8); \
        *reinterpret_cast<float4*>(areg + 12) = *reinterpret_cast<const float4*>(_p + 12); \
    } while (0)
    #define STSA(buf) do { \
        __half hh[16], ll[16]; \
        _Pragma("unroll") \
        for (int q = 0; q < 16; q++) { \
            hh[q] = __float2half_rn(areg[q]); \
            ll[q] = __float2half_rn(areg[q] - __half2float(hh[q])); \
        } \
        uint32_t _o = (uint32_t)((buf) * HSTAGE + arr * HSTRIDE + acb); \
        __half* _ah = hsm + _o; \
        __half* _al = hsm + _o + HARR; \
        *reinterpret_cast<uint4*>(_ah)     = *reinterpret_cast<uint4*>(hh); \
        *reinterpret_cast<uint4*>(_ah + 8) = *reinterpret_cast<uint4*>(hh + 8); \
        *reinterpret_cast<uint4*>(_al)     = *reinterpret_cast<uint4*>(ll); \
        *reinterpret_cast<uint4*>(_al + 8) = *reinterpret_cast<uint4*>(ll + 8); \
    } while (0)

    LDGA(0);
    STSA(0);
    zb_loads(sbase, 0, Bh, Bl, col0, kdim, 0, tid);

    for (int c = 0; c < nch; c++) {
        if (c + 1 < nch) {
            LDGA((c + 1) * 32);
            zb_loads(sbase, (c + 1) & 1, Bh, Bl, col0, kdim, (c + 1) * 32, tid);
            CPWAIT1();
        } else {
            CPWAIT0();
        }
        __syncthreads();
        const uint32_t sb = sbase + (uint32_t)((c & 1) * HSTAGE) * 2u;
        #pragma unroll
        for (int ks = 0; ks < 2; ks++) {
            const int k0 = ks * 16;
            uint32_t ahi[2][4], alo[2][4];
            #pragma unroll
            for (int mt = 0; mt < 2; mt++) {
                uint32_t aaddr = sb + (uint32_t)(((warp_m * 32 + mt * 16 + (lane & 15)) * HSTRIDE)
                                                 + k0 + (lane >> 4) * 8) * 2u;
                ldsm4(ahi[mt], aaddr);
                ldsm4(alo[mt], aaddr + HARR * 2u);
            }
            #pragma unroll
            for (int np = 0; np < 4; np++) {
                uint32_t bh[4], bl[4];
                uint32_t baddr = sb + 2u * HARR * 2u +
                    (uint32_t)(((warp_n * 64 + np * 16 + (quad >> 1) * 8 + (lane & 7)) * HSTRIDE)
                               + k0 + (quad & 1) * 8) * 2u;
                ldsm4(bh, baddr);
                ldsm4(bl, baddr + HARR * 2u);
                #pragma unroll
                for (int mt = 0; mt < 2; mt++)
                    #pragma unroll
                    for (int g = 0; g < 2; g++) {
                        const int nt = np * 2 + g;
                        uint32_t vh[2] = {bh[g * 2], bh[g * 2 + 1]};
                        uint32_t vl[2] = {bl[g * 2], bl[g * 2 + 1]};
                        mma_f16(acc[mt][nt], ahi[mt], vh);
                        mma_f16(acc[mt][nt], ahi[mt], vl);
                        mma_f16(acc[mt][nt], alo[mt], vh);
                    }
            }
        }
        if (c + 1 < nch) STSA((c + 1) & 1);
        __syncthreads();
    }

    const int tr = lane >> 2, tc = (lane & 3) * 2;
    #pragma unroll
    for (int mt = 0; mt < 2; mt++)
        #pragma unroll
        for (int h = 0; h < 2; h++) {
            int row = row0 + warp_m * 32 + mt * 16 + h * 8 + tr;
            #pragma unroll
            for (int nt = 0; nt < 8; nt++) {
                int col = col0 + warp_n * 64 + nt * 8 + tc;
                float v0 = acc[mt][nt][h * 2 + 0] + bias[col];
                float v1 = acc[mt][nt][h * 2 + 1] + bias[col + 1];
                size_t o = (size_t)row * ldc + col;
                *reinterpret_cast<float2*>(C + o) = make_float2(v0, v1);
                __nv_bfloat162 hp = __floats2bfloat162_rn(v0, v1);
                *reinterpret_cast<uint32_t*>(Chi + o) = *reinterpret_cast<uint32_t*>(&hp);
            }
        }
}

// ===========================================================================
// fp16x3 GEMM pre-split A and B (Y)
__device__ __forceinline__ void h_loads(uint32_t sbase, int buf,
    const __half* __restrict__ Ah, const __half* __restrict__ Al,
    const __half* __restrict__ Bh, const __half* __restrict__ Bl,
    int row0, int col0, int kdim, int kc, int tid)
{
    #pragma unroll
    for (int i = 0; i < 2; i++) {
        int seg = tid + i * 256;
        int rr = seg >> 2, cc = (seg & 3) * 8;
        uint32_t so = sbase + (uint32_t)(buf * HSTAGE + rr * HSTRIDE + cc) * 2u;
        CP16(so,                  Ah + (size_t)(row0 + rr) * kdim + kc + cc);
        CP16(so + HARR * 2u,      Al + (size_t)(row0 + rr) * kdim + kc + cc);
        CP16(so + 2u * HARR * 2u, Bh + (size_t)(col0 + rr) * kdim + kc + cc);
        CP16(so + 3u * HARR * 2u, Bl + (size_t)(col0 + rr) * kdim + kc + cc);
    }
    CPCOMMIT();
}

__global__ __launch_bounds__(256, 2) void k_hgemm(
    const __half* __restrict__ Ah, const __half* __restrict__ Al,
    const __half* __restrict__ Bh, const __half* __restrict__ Bl,
    const float* __restrict__ bias, float* __restrict__ C,
    int ldc, int kdim)
{
    extern __shared__ __half hsm[];
    const int tid = threadIdx.x, lane = tid & 31, wid = tid >> 5;
    const int warp_m = wid & 3, warp_n = wid >> 2;
    const int row0 = blockIdx.y * 128, col0 = blockIdx.x * 128;
    const uint32_t sbase = smem_u32(hsm);
    const int quad = lane >> 3;

    float acc[2][8][4];
    #pragma unroll
    for (int a = 0; a < 2; a++)
        #pragma unroll
        for (int b = 0; b < 8; b++)
            #pragma unroll
            for (int c = 0; c < 4; c++) acc[a][b][c] = 0.0f;

    const int nch = kdim >> 5;
    h_loads(sbase, 0, Ah, Al, Bh, Bl, row0, col0, kdim, 0, tid);

    for (int c = 0; c < nch; c++) {
        if (c + 1 < nch) {
            h_loads(sbase, (c + 1) & 1, Ah, Al, Bh, Bl, row0, col0, kdim, (c + 1) * 32, tid);
            CPWAIT1();
        } else {
            CPWAIT0();
        }
        __syncthreads();
        const uint32_t sb = sbase + (uint32_t)((c & 1) * HSTAGE) * 2u;
        #pragma unroll
        for (int ks = 0; ks < 2; ks++) {
            const int k0 = ks * 16;
            uint32_t ahi[2][4], alo[2][4];
            #pragma unroll
            for (int mt = 0; mt < 2; mt++) {
                uint32_t aaddr = sb + (uint32_t)(((warp_m * 32 + mt * 16 + (lane & 15)) * HSTRIDE)
                                                 + k0 + (lane >> 4) * 8) * 2u;
                ldsm4(ahi[mt], aaddr);
                ldsm4(alo[mt], aaddr + HARR * 2u);
            }
            #pragma unroll
            for (int np = 0; np < 4; np++) {
                uint32_t bh[4], bl[4];
                uint32_t baddr = sb + 2u * HARR * 2u +
                    (uint32_t)(((warp_n * 64 + np * 16 + (quad >> 1) * 8 + (lane & 7)) * HSTRIDE)
                               + k0 + (quad & 1) * 8) * 2u;
                ldsm4(bh, baddr);
                ldsm4(bl, baddr + HARR * 2u);
                #pragma unroll
                for (int mt = 0; mt < 2; mt++)
                    #pragma unroll
                    for (int g = 0; g < 2; g++) {
                        const int nt = np * 2 + g;
                        uint32_t vh[2] = {bh[g * 2], bh[g * 2 + 1]};
                        uint32_t vl[2] = {bl[g * 2], bl[g * 2 + 1]};
                        mma_f16(acc[mt][nt], ahi[mt], vh);
                        mma_f16(acc[mt][nt], ahi[mt], vl);
                        mma_f16(acc[mt][nt], alo[mt], vh);
                    }
            }
        }
        __syncthreads();
    }

    const int tr = lane >> 2, tc = (lane & 3) * 2;
    #pragma unroll
    for (int mt = 0; mt < 2; mt++)
        #pragma unroll
        for (int h = 0; h < 2; h++) {
            int row = row0 + warp_m * 32 + mt * 16 + h * 8 + tr;
            #pragma unroll
            for (int nt = 0; nt < 8; nt++) {
                int col = col0 + warp_n * 64 + nt * 8 + tc;
                float v0 = acc[mt][nt][h * 2 + 0] + bias[col];
                float v1 = acc[mt][nt][h * 2 + 1] + bias[col + 1];
                *reinterpret_cast<float2*>(C + (size_t)row * ldc + col) = make_float2(v0, v1);
            }
        }
}

// ===========================================================================
// dist = sqr - 2 * (zh @ cbh^T), single bf16 product, fp16 output (32 MB).
#define CSTRIDE 40
#define CARR (128 * CSTRIDE)

__device__ __forceinline__ void cov_loads(uint32_t sbase, int buf,
                                          int row0, int code0, int kc, int tid)
{
    #pragma unroll
    for (int t = 0; t < 2; t++) {
        int seg = tid + t * 256;
        int rr = seg >> 2, cc = (seg & 3) * 8;
        uint32_t so = sbase + (uint32_t)(buf * 2 * CARR + rr * CSTRIDE + cc) * 2u;
        CP16(so,             g_zh  + (size_t)(row0 + rr) * DEMB + kc + cc);
        CP16(so + CARR * 2u, g_cbh + (size_t)(code0 + rr) * DEMB + kc + cc);
    }
    CPCOMMIT();
}

__global__ __launch_bounds__(256, 2) void k_cov(int rybase)
{
    __shared__ __align__(16) __nv_bfloat16 sm[2][2][CARR];
    __shared__ float s_sqr[128];
    const int tid = threadIdx.x, lane = tid & 31, wid = tid >> 5;
    const int warp_m = wid & 3, warp_n = wid >> 2;
    const int row0 = (blockIdx.y + rybase) * 128, code0 = blockIdx.x * 128;
    const uint32_t sbase = smem_u32(&sm[0][0][0]);
    const int quad = lane >> 3;

    if (tid < 128) s_sqr[tid] = g_sqr[code0 + tid];

    float acc[2][8][4];
    #pragma unroll
    for (int a = 0; a < 2; a++)
        #pragma unroll
        for (int b = 0; b < 8; b++)
            #pragma unroll
            for (int c = 0; c < 4; c++) acc[a][b][c] = 0.0f;

    cov_loads(sbase, 0, row0, code0, 0, tid);
    const int nch = DEMB >> 5;
    for (int c = 0; c < nch; c++) {
        if (c + 1 < nch) { cov_loads(sbase, (c + 1) & 1, row0, code0, (c + 1) * 32, tid); CPWAIT1(); }
        else CPWAIT0();
        __syncthreads();
        const uint32_t sb = sbase + (uint32_t)((c & 1) * 2 * CARR) * 2u;
        #pragma unroll
        for (int ks = 0; ks < 2; ks++) {
            const int k0 = ks * 16;
            uint32_t a[2][4];
            #pragma unroll
            for (int mt = 0; mt < 2; mt++)
                ldsm4(a[mt], sb + (uint32_t)(((warp_m * 32 + mt * 16 + (lane & 15)) * CSTRIDE)
                                             + k0 + (lane >> 4) * 8) * 2u);
            #pragma unroll
            for (int np = 0; np < 4; np++) {
                uint32_t b[4];
                ldsm4(b, sb + CARR * 2u +
                      (uint32_t)(((warp_n * 64 + np * 16 + (quad >> 1) * 8 + (lane & 7)) * CSTRIDE)
                                 + k0 + (quad & 1) * 8) * 2u);
                #pragma unroll
                for (int mt = 0; mt < 2; mt++)
                    #pragma unroll
                    for (int g = 0; g < 2; g++) {
                        uint32_t vb[2] = {b[g * 2], b[g * 2 + 1]};
                        mma_bf16(acc[mt][np * 2 + g], a[mt], vb);
                    }
            }
        }
        __syncthreads();
    }

    const int tr = lane >> 2, tc = (lane & 3) * 2;
    #pragma unroll
    for (int mt = 0; mt < 2; mt++)
        #pragma unroll
        for (int h = 0; h < 2; h++) {
            int row = row0 + warp_m * 32 + mt * 16 + h * 8 + tr;
            #pragma unroll
            for (int nt = 0; nt < 8; nt++) {
                int colL = warp_n * 64 + nt * 8 + tc;
                float d0 = fmaf(-2.0f, acc[mt][nt][h * 2 + 0], s_sqr[colL]);
                float d1 = fmaf(-2.0f, acc[mt][nt][h * 2 + 1], s_sqr[colL + 1]);
                __half2 hd;
                hd.x = __float2half_rn(d0);
                hd.y = __float2half_rn(d1);
                *reinterpret_cast<__half2*>(g_dist + (size_t)row * KCB + code0 + colL) = hd;
            }
        }
}

// ===========================================================================
// Refine + fused scatter + fused gather. Block per row (256 threads).
__global__ __launch_bounds__(256) void k_refine(
    const float* __restrict__ cb, float* __restrict__ out)
{
    __shared__ float s_z[DEMB];
    __shared__ float s_wmin[8];
    __shared__ float s_wsq[8];
    __shared__ int   s_cand[64];
    __shared__ int   s_ncand;
    __shared__ unsigned long long s_best;

    const int row = blockIdx.x;
    const int t = threadIdx.x;
    const int wid = t >> 5, lane = t & 31;

    float zval = g_z[(size_t)row * DEMB + t];
    s_z[t] = zval;
    if (t == 0) { s_ncand = 0; s_best = 0xFFFFFFFFFFFFFFFFull; }

    const __half2* drow = reinterpret_cast<const __half2*>(g_dist + (size_t)row * KCB);
    __half2 p0 = drow[t];
    __half2 p1 = drow[256 + t];
    float dt[4];
    int   ci[4];
    dt[0] = __half2float(p0.x); ci[0] = 2 * t;
    dt[1] = __half2float(p0.y); ci[1] = 2 * t + 1;
    dt[2] = __half2float(p1.x); ci[2] = 512 + 2 * t;
    dt[3] = __half2float(p1.y); ci[3] = 512 + 2 * t + 1;
    float lm = fminf(fminf(dt[0], dt[1]), fminf(dt[2], dt[3]));
    #pragma unroll
    for (int o = 16; o > 0; o >>= 1) lm = fminf(lm, __shfl_xor_sync(0xffffffffu, lm, o));
    if (lane == 0) s_wmin[wid] = lm;
    __syncthreads();
    float thr = s_wmin[0];
    #pragma unroll
    for (int w = 1; w < 8; w++) thr = fminf(thr, s_wmin[w]);
    thr += MARGIN;

    #pragma unroll
    for (int i = 0; i < 4; i++) {
        if (dt[i] <= thr) {
            int idx = atomicAdd(&s_ncand, 1);
            if (idx < 64) s_cand[idx] = ci[i];
        }
    }
    __syncthreads();
    const int nc = s_ncand;

    if (nc <= 64) {
        for (int cc = wid; cc < nc; cc += 8) {
            int c = s_cand[cc];
            const float* cbr = cb + (size_t)c * DEMB;
            float dot = 0.0f;
            #pragma unroll
            for (int j = 0; j < 8; j++) dot = fmaf(s_z[lane + 32 * j], cbr[lane + 32 * j], dot);
            #pragma unroll
            for (int o = 16; o > 0; o >>= 1) dot += __shfl_xor_sync(0xffffffffu, dot, o);
            if (lane == 0) {
                float d = fmaf(-2.0f, dot, g_sqr[c]);
                unsigned u = __float_as_uint(d);
                u = (u & 0x80000000u) ? ~u : (u | 0x80000000u);
                atomicMin(&s_best, ((unsigned long long)u << 32) | (unsigned)c);
            }
        }
    } else {
        for (int c = wid; c < KCB; c += 8) {
            const float* cbr = cb + (size_t)c * DEMB;
            float dot = 0.0f;
            #pragma unroll
            for (int j = 0; j < 8; j++) dot = fmaf(s_z[lane + 32 * j], cbr[lane + 32 * j], dot);
            #pragma unroll
            for (int o = 16; o > 0; o >>= 1) dot += __shfl_xor_sync(0xffffffffu, dot, o);
            if (lane == 0) {
                float d = fmaf(-2.0f, dot, g_sqr[c]);
                unsigned u = __float_as_uint(d);
                u = (u & 0x80000000u) ? ~u : (u | 0x80000000u);
                atomicMin(&s_best, ((unsigned long long)u << 32) | (unsigned)c);
            }
        }
    }
    __syncthreads();

    unsigned long long p = s_best;
    int code = (int)(unsigned)(p & 0xFFFFFFFFull);
    unsigned ue = (unsigned)(p >> 32);
    float dmin = (ue & 0x80000000u) ? __uint_as_float(ue & 0x7FFFFFFFu)
                                    : __uint_as_float(~ue);

    // fused gather: x[row] = Y[code]
    {
        const float4* ysrc = reinterpret_cast<const float4*>(g_Y + (size_t)code * DIN);
        float4* xdst = reinterpret_cast<float4*>(out + OFF_X + (size_t)row * DIN);
        xdst[t] = ysrc[t];
    }

    // fused scatter: segment-sum z, counts, loss
    atomicAdd(&g_upd[(size_t)code * DEMB + t], zval);
    float sq = zval * zval;
    #pragma unroll
    for (int o = 16; o > 0; o >>= 1) sq += __shfl_xor_sync(0xffffffffu, sq, o);
    if (lane == 0) s_wsq[wid] = sq;
    __syncthreads();
    if (t == 0) {
        float tot = 0.0f;
        #pragma unroll
        for (int w = 0; w < 8; w++) tot += s_wsq[w];
        out[OFF_CODES + row] = (float)code;
        atomicAdd(&g_loss, tot + dmin);
        atomicAdd(&g_cnt[code], 1.0f);
    }
}

// ===========================================================================
// Fused prep: one codebook read -> sqr, bf16 cb, fp16 hi/lo cb; zero accs.
__global__ __launch_bounds__(256) void k_prep(const float* __restrict__ cb) {
    int k = blockIdx.x, t = threadIdx.x;
    float v = cb[k * DEMB + t];
    g_cbh[k * DEMB + t] = __float2bfloat16(v);
    __half h = __float2half_rn(v);
    g_cbh16[k * DEMB + t] = h;
    g_cbl16[k * DEMB + t] = __float2half_rn(v - __half2float(h));
    g_upd[k * DEMB + t] = 0.0f;

    float s = v * v;
    #pragma unroll
    for (int o = 16; o > 0; o >>= 1) s += __shfl_xor_sync(0xffffffffu, s, o);
    __shared__ float wsum[8];
    if ((t & 31) == 0) wsum[t >> 5] = s;
    __syncthreads();
    if (t == 0) {
        float tot = 0.0f;
        #pragma unroll
        for (int w = 0; w < 8; w++) tot += wsum[w];
        g_sqr[k] = tot;
        g_cnt[k] = 0.0f;
        if (k == 0) g_loss = 0.0f;
    }
}

// Coalesced tiled transpose + fp16 hi/lo split: dst[C,R] = split(src[R,C]^T).
// 32x32 tiles, 256 threads (32x8, 4 rows each). R, C multiples of 32.
__global__ __launch_bounds__(256) void k_trsplit16(
    const float* __restrict__ src, __half* __restrict__ hi,
    __half* __restrict__ lo, int R, int C)
{
    __shared__ float tile[32][33];
    const int bx = blockIdx.x * 32;   // col base in src (C dim)
    const int by = blockIdx.y * 32;   // row base in src (R dim)
    const int tx = threadIdx.x & 31, ty = threadIdx.x >> 5;   // 32 x 8

    #pragma unroll
    for (int i = 0; i < 4; i++) {
        int r = ty * 4 + i;
        tile[r][tx] = src[(size_t)(by + r) * C + bx + tx];
    }
    __syncthreads();
    #pragma unroll
    for (int i = 0; i < 4; i++) {
        int ro = ty * 4 + i;           // output row (src col)
        float v = tile[tx][ro];
        __half h = __float2half_rn(v);
        size_t o = (size_t)(bx + ro) * R + by + tx;
        hi[o] = h;
        lo[o] = __float2half_rn(v - __half2float(h));
    }
}

// ---------------------------------------------------------------------------
__global__ __launch_bounds__(1024) void k_final_small(
    const float* __restrict__ ema_size_in, float* __restrict__ out)
{
    __shared__ float sh[1024];
    int t = threadIdx.x;
    float cnt = g_cnt[t];
    float esz = ema_size_in[t] + ALPHA * (cnt - ema_size_in[t]);
    out[OFF_EMA_SIZE + t] = esz;

    sh[t] = esz;
    __syncthreads();
    for (int s = 512; s > 0; s >>= 1) {
        if (t < s) sh[t] += sh[t + s];
        __syncthreads();
    }
    float n = sh[0];
    __syncthreads();

    float coef = n / (n + (float)KCB * EPSV);
    g_size[t]  = coef * (esz + EPSV);

    float p = cnt * (1.0f / (float)NROWS);
    float e = (cnt > 0.0f) ? (-p * logf(p)) : 0.0f;
    sh[t] = e;
    __syncthreads();
    for (int s = 512; s > 0; s >>= 1) {
        if (t < s) sh[t] += sh[t + s];
        __syncthreads();
    }
    if (t == 0) {
        out[OFF_ENT]    = sh[0] / logf(2.0f);
        out[OFF_EMB]    = g_loss;
        out[OFF_COMMIT] = g_loss;
    }
}

__global__ void k_ema(const float* __restrict__ ema_vecs_in, float* __restrict__ out) {
    int i = blockIdx.x * blockDim.x + threadIdx.x;
    float v = ema_vecs_in[i] + ALPHA * (g_upd[i] - ema_vecs_in[i]);
    out[OFF_EMA_VECS + i] = v;
    out[OFF_WEIGHT + i]   = v / g_size[i >> 8];
}

// ---------------------------------------------------------------------------
extern "C" void kernel_launch(void* const* d_in, const int* in_sizes, int n_in,
                              void* d_out, int out_size) {
    const float* input    = (const float*)d_in[0];
    const float* W_send   = (const float*)d_in[1];
    const float* b_send   = (const float*)d_in[2];
    const float* W_recv   = (const float*)d_in[3];
    const float* b_recv   = (const float*)d_in[4];
    const float* codebook = (const float*)d_in[5];
    const float* ema_vecs = (const float*)d_in[6];
    const float* ema_size = (const float*)d_in[7];
    float* out = (float*)d_out;

    float *z_ptr, *Y_ptr;
    __half *wsh, *wsl, *wrh, *wrl, *cb16h, *cb16l;
    __nv_bfloat16 *zh;
    cudaGetSymbolAddress((void**)&z_ptr, g_z);
    cudaGetSymbolAddress((void**)&Y_ptr, g_Y);
    cudaGetSymbolAddress((void**)&wsh, g_wsh);   cudaGetSymbolAddress((void**)&wsl, g_wsl);
    cudaGetSymbolAddress((void**)&wrh, g_wrh);   cudaGetSymbolAddress((void**)&wrl, g_wrl);
    cudaGetSymbolAddress((void**)&cb16h, g_cbh16); cudaGetSymbolAddress((void**)&cb16l, g_cbl16);
    cudaGetSymbolAddress((void**)&zh, g_zh);

    static cudaStream_t s1 = nullptr, s2 = nullptr;
    static cudaEvent_t eFork = nullptr, eZ1 = nullptr, eZ2 = nullptr, eE = nullptr;
    if (!s1) {
        cudaStreamCreateWithFlags(&s1, cudaStreamNonBlocking);
        cudaStreamCreateWithFlags(&s2, cudaStreamNonBlocking);
        cudaEventCreateWithFlags(&eFork, cudaEventDisableTiming);
        cudaEventCreateWithFlags(&eZ1,   cudaEventDisableTiming);
        cudaEventCreateWithFlags(&eZ2,   cudaEventDisableTiming);
        cudaEventCreateWithFlags(&eE,    cudaEventDisableTiming);
        cudaFuncSetAttribute(k_zgemm, cudaFuncAttributeMaxDynamicSharedMemorySize, HSMEM_BYTES);
        cudaFuncSetAttribute(k_hgemm, cudaFuncAttributeMaxDynamicSharedMemorySize, HSMEM_BYTES);
    }

    // fork worker streams off the capture/default stream
    cudaEventRecord(eFork, 0);
    cudaStreamWaitEvent(s1, eFork, 0);
    cudaStreamWaitEvent(s2, eFork, 0);

    // s1: z chain in two row-halves (grid 8x32 for transpose of [1024,256])
    k_trsplit16<<<dim3(DEMB / 32, DIN / 32), 256, 0, s1>>>(W_send, wsh, wsl, DIN, DEMB);
    k_zgemm<<<dim3(2, 64), 256, HSMEM_BYTES, s1>>>(input, wsh, wsl, b_send,
                                                   z_ptr, zh, DEMB, DIN, 0);
    cudaEventRecord(eZ1, s1);
    k_zgemm<<<dim3(2, 64), 256, HSMEM_BYTES, s1>>>(input, wsh, wsl, b_send,
                                                   z_ptr, zh, DEMB, DIN, 64);
    cudaEventRecord(eZ2, s1);

    // s2: fused prep, Y, then cov halves pipelined against z, then tail
    k_prep<<<KCB, 256, 0, s2>>>(codebook);
    k_trsplit16<<<dim3(DIN / 32, DEMB / 32), 256, 0, s2>>>(W_recv, wrh, wrl, DEMB, DIN);
    k_hgemm<<<dim3(8, 8), 256, HSMEM_BYTES, s2>>>(cb16h, cb16l, wrh, wrl, b_recv,
                                                  Y_ptr, DIN, DEMB);
    cudaStreamWaitEvent(s2, eZ1, 0);
    k_cov<<<dim3(8, 64), 256, 0, s2>>>(0);      // rows 0..8191 (overlaps z half 2)
    cudaStreamWaitEvent(s2, eZ2, 0);
    k_cov<<<dim3(8, 64), 256, 0, s2>>>(64);     // rows 8192..16383
    k_refine<<<NROWS, 256, 0, s2>>>(codebook, out);
    k_final_small<<<1, 1024, 0, s2>>>(ema_size, out);
    k_ema<<<1024, 256, 0, s2>>>(ema_vecs, out);
    cudaEventRecord(eE, s2);

    // join back to the default/capture stream
    cudaStreamWaitEvent(0, eE, 0);
}

// round 17
// speedup vs baseline: 1.2894x; 1.2894x over previous
#include <cuda_runtime.h>
#include <cuda_bf16.h>
#include <cuda_fp16.h>
#include <math.h>
#include <stdint.h>

// Problem constants
#define NROWS 16384
#define DIN   1024
#define DEMB  256
#define KCB   1024
#define ALPHA 0.01f
#define EPSV  1e-5f
#define MARGIN 4.0f

// Output layout (float32, tuple order concatenated)
#define OFF_X        ((size_t)0)
#define OFF_CODES    ((size_t)16777216)
#define OFF_EMB      ((size_t)16793600)
#define OFF_COMMIT   ((size_t)16793601)
#define OFF_ENT      ((size_t)16793602)
#define OFF_EMA_VECS ((size_t)16793603)
#define OFF_EMA_SIZE ((size_t)17055747)
#define OFF_WEIGHT   ((size_t)17056771)

// ---------------------------------------------------------------------------
// Scratch (device globals; no allocations allowed)
__device__ float g_z[NROWS * DEMB];
__device__ float g_sqr[KCB];
__device__ float g_upd[KCB * DEMB];
__device__ float g_cnt[KCB];
__device__ float g_loss;
__device__ float g_size[KCB];
__device__ float g_Y[KCB * DIN];
__device__ __half g_dist[NROWS * KCB];        // 32 MB approx distances (fp16)
__device__ __nv_bfloat16 g_zh[NROWS * DEMB];  // bf16 z for cov
__device__ __nv_bfloat16 g_cbh[KCB * DEMB];   // bf16 codebook for cov
// fp16 hi/lo operand splits
__device__ __half g_wsh[DEMB * DIN],  g_wsl[DEMB * DIN];      // W_send^T [256,1024]
__device__ __half g_wrh[DIN * DEMB],  g_wrl[DIN * DEMB];      // W_recv^T [1024,256]
__device__ __half g_cbh16[KCB * DEMB], g_cbl16[KCB * DEMB];   // codebook

// ---------------------------------------------------------------------------
__device__ __forceinline__ uint32_t smem_u32(const void* p) {
    uint32_t a;
    asm("{ .reg .u64 t; cvta.to.shared.u64 t, %1; cvt.u32.u64 %0, t; }" : "=r"(a) : "l"(p));
    return a;
}
__device__ __forceinline__ void ldsm4(uint32_t* r, uint32_t addr) {
    asm volatile("ldmatrix.sync.aligned.m8n8.x4.shared.b16 {%0,%1,%2,%3}, [%4];"
                 : "=r"(r[0]), "=r"(r[1]), "=r"(r[2]), "=r"(r[3]) : "r"(addr));
}
__device__ __forceinline__ void mma_f16(float* c, const uint32_t* a, const uint32_t* b) {
    asm volatile("mma.sync.aligned.m16n8k16.row.col.f32.f16.f16.f32 "
                 "{%0,%1,%2,%3}, {%4,%5,%6,%7}, {%8,%9}, {%0,%1,%2,%3};"
                 : "+f"(c[0]), "+f"(c[1]), "+f"(c[2]), "+f"(c[3])
                 : "r"(a[0]), "r"(a[1]), "r"(a[2]), "r"(a[3]), "r"(b[0]), "r"(b[1]));
}
__device__ __forceinline__ void mma_bf16(float* c, const uint32_t* a, const uint32_t* b) {
    asm volatile("mma.sync.aligned.m16n8k16.row.col.f32.bf16.bf16.f32 "
                 "{%0,%1,%2,%3}, {%4,%5,%6,%7}, {%8,%9}, {%0,%1,%2,%3};"
                 : "+f"(c[0]), "+f"(c[1]), "+f"(c[2]), "+f"(c[3])
                 : "r"(a[0]), "r"(a[1]), "r"(a[2]), "r"(a[3]), "r"(b[0]), "r"(b[1]));
}
#define CP16(sm, gp) asm volatile("cp.async.ca.shared.global [%0], [%1], 16;" :: "r"(sm), "l"(gp))
#define CPCOMMIT()   asm volatile("cp.async.commit_group;" ::: "memory")
#define CPWAIT0()    asm volatile("cp.async.wait_group 0;" ::: "memory")
#define CPWAIT1()    asm volatile("cp.async.wait_group 1;" ::: "memory")

// smem tile geometry (validated R8-R16)
#define HSTRIDE 40
#define HARR (128 * HSTRIDE)
#define HSTAGE (4 * HARR)
#define HSMEM_BYTES (2 * HSTAGE * 2)  // 81920

// ===========================================================================
// z GEMM (fp16x3) with fused A split (fp32 LDG -> in-register hi/lo -> STS).
__device__ __forceinline__ void zb_loads(uint32_t sbase, int buf,
    const __half* __restrict__ Bh, const __half* __restrict__ Bl,
    int col0, int kdim, int kc, int tid)
{
    #pragma unroll
    for (int i = 0; i < 2; i++) {
        int seg = tid + i * 256;
        int rr = seg >> 2, cc = (seg & 3) * 8;
        uint32_t so = sbase + (uint32_t)(buf * HSTAGE + rr * HSTRIDE + cc) * 2u;
        CP16(so + 2u * HARR * 2u, Bh + (size_t)(col0 + rr) * kdim + kc + cc);
        CP16(so + 3u * HARR * 2u, Bl + (size_t)(col0 + rr) * kdim + kc + cc);
    }
    CPCOMMIT();
}

__global__ __launch_bounds__(256, 2) void k_zgemm(
    const float* __restrict__ A,
    const __half* __restrict__ Bh, const __half* __restrict__ Bl,
    const float* __restrict__ bias, float* __restrict__ C,
    __nv_bfloat16* __restrict__ Chi, int ldc, int kdim)
{
    extern __shared__ __half hsm[];
    const int tid = threadIdx.x, lane = tid & 31, wid = tid >> 5;
    const int warp_m = wid & 3, warp_n = wid >> 2;
    const int row0 = blockIdx.y * 128, col0 = blockIdx.x * 128;
    const uint32_t sbase = smem_u32(hsm);
    const int quad = lane >> 3;

    const int arr = tid >> 1;
    const int acb = (tid & 1) * 16;

    float areg[16];
    float acc[2][8][4];
    #pragma unroll
    for (int a = 0; a < 2; a++)
        #pragma unroll
        for (int b = 0; b < 8; b++)
            #pragma unroll
            for (int c = 0; c < 4; c++) acc[a][b][c] = 0.0f;

    const int nch = kdim >> 5;
    const float* Abase = A + (size_t)(row0 + arr) * kdim + acb;
    #define LDGA(kc) do { \
        const float* _p = Abase + (kc); \
        *reinterpret_cast<float4*>(areg + 0)  = *reinterpret_cast<const float4*>(_p); \
        *reinterpret_cast<float4*>(areg + 4)  = *reinterpret_cast<const float4*>(_p + 4); \
        *reinterpret_cast<float4*>(areg + 8)  = *reinterpret_cast<const float4*>(_p + 8); \
        *reinterpret_cast<float4*>(areg + 12) = *reinterpret_cast<const float4*>(_p + 12); \
    } while (0)
    #define STSA(buf) do { \
        __half hh[16], ll[16]; \
        _Pragma("unroll") \
        for (int q = 0; q < 16; q++) { \
            hh[q] = __float2half_rn(areg[q]); \
            ll[q] = __float2half_rn(areg[q] - __half2float(hh[q])); \
        } \
        uint32_t _o = (uint32_t)((buf) * HSTAGE + arr * HSTRIDE + acb); \
        __half* _ah = hsm + _o; \
        __half* _al = hsm + _o + HARR; \
        *reinterpret_cast<uint4*>(_ah)     = *reinterpret_cast<uint4*>(hh); \
        *reinterpret_cast<uint4*>(_ah + 8) = *reinterpret_cast<uint4*>(hh + 8); \
        *reinterpret_cast<uint4*>(_al)     = *reinterpret_cast<uint4*>(ll); \
        *reinterpret_cast<uint4*>(_al + 8) = *reinterpret_cast<uint4*>(ll + 8); \
    } while (0)

    LDGA(0);
    STSA(0);
    zb_loads(sbase, 0, Bh, Bl, col0, kdim, 0, tid);

    for (int c = 0; c < nch; c++) {
        if (c + 1 < nch) {
            LDGA((c + 1) * 32);
            zb_loads(sbase, (c + 1) & 1, Bh, Bl, col0, kdim, (c + 1) * 32, tid);
            CPWAIT1();
        } else {
            CPWAIT0();
        }
        __syncthreads();
        const uint32_t sb = sbase + (uint32_t)((c & 1) * HSTAGE) * 2u;
        #pragma unroll
        for (int ks = 0; ks < 2; ks++) {
            const int k0 = ks * 16;
            uint32_t ahi[2][4], alo[2][4];
            #pragma unroll
            for (int mt = 0; mt < 2; mt++) {
                uint32_t aaddr = sb + (uint32_t)(((warp_m * 32 + mt * 16 + (lane & 15)) * HSTRIDE)
                                                 + k0 + (lane >> 4) * 8) * 2u;
                ldsm4(ahi[mt], aaddr);
                ldsm4(alo[mt], aaddr + HARR * 2u);
            }
            #pragma unroll
            for (int np = 0; np < 4; np++) {
                uint32_t bh[4], bl[4];
                uint32_t baddr = sb + 2u * HARR * 2u +
                    (uint32_t)(((warp_n * 64 + np * 16 + (quad >> 1) * 8 + (lane & 7)) * HSTRIDE)
                               + k0 + (quad & 1) * 8) * 2u;
                ldsm4(bh, baddr);
                ldsm4(bl, baddr + HARR * 2u);
                #pragma unroll
                for (int mt = 0; mt < 2; mt++)
                    #pragma unroll
                    for (int g = 0; g < 2; g++) {
                        const int nt = np * 2 + g;
                        uint32_t vh[2] = {bh[g * 2], bh[g * 2 + 1]};
                        uint32_t vl[2] = {bl[g * 2], bl[g * 2 + 1]};
                        mma_f16(acc[mt][nt], ahi[mt], vh);
                        mma_f16(acc[mt][nt], ahi[mt], vl);
                        mma_f16(acc[mt][nt], alo[mt], vh);
                    }
            }
        }
        if (c + 1 < nch) STSA((c + 1) & 1);
        __syncthreads();
    }

    const int tr = lane >> 2, tc = (lane & 3) * 2;
    #pragma unroll
    for (int mt = 0; mt < 2; mt++)
        #pragma unroll
        for (int h = 0; h < 2; h++) {
            int row = row0 + warp_m * 32 + mt * 16 + h * 8 + tr;
            #pragma unroll
            for (int nt = 0; nt < 8; nt++) {
                int col = col0 + warp_n * 64 + nt * 8 + tc;
                float v0 = acc[mt][nt][h * 2 + 0] + bias[col];
                float v1 = acc[mt][nt][h * 2 + 1] + bias[col + 1];
                size_t o = (size_t)row * ldc + col;
                *reinterpret_cast<float2*>(C + o) = make_float2(v0, v1);
                __nv_bfloat162 hp = __floats2bfloat162_rn(v0, v1);
                *reinterpret_cast<uint32_t*>(Chi + o) = *reinterpret_cast<uint32_t*>(&hp);
            }
        }
}

// ===========================================================================
// fp16x3 GEMM pre-split A and B (Y)
__device__ __forceinline__ void h_loads(uint32_t sbase, int buf,
    const __half* __restrict__ Ah, const __half* __restrict__ Al,
    const __half* __restrict__ Bh, const __half* __restrict__ Bl,
    int row0, int col0, int kdim, int kc, int tid)
{
    #pragma unroll
    for (int i = 0; i < 2; i++) {
        int seg = tid + i * 256;
        int rr = seg >> 2, cc = (seg & 3) * 8;
        uint32_t so = sbase + (uint32_t)(buf * HSTAGE + rr * HSTRIDE + cc) * 2u;
        CP16(so,                  Ah + (size_t)(row0 + rr) * kdim + kc + cc);
        CP16(so + HARR * 2u,      Al + (size_t)(row0 + rr) * kdim + kc + cc);
        CP16(so + 2u * HARR * 2u, Bh + (size_t)(col0 + rr) * kdim + kc + cc);
        CP16(so + 3u * HARR * 2u, Bl + (size_t)(col0 + rr) * kdim + kc + cc);
    }
    CPCOMMIT();
}

__global__ __launch_bounds__(256, 2) void k_hgemm(
    const __half* __restrict__ Ah, const __half* __restrict__ Al,
    const __half* __restrict__ Bh, const __half* __restrict__ Bl,
    const float* __restrict__ bias, float* __restrict__ C,
    int ldc, int kdim)
{
    extern __shared__ __half hsm[];
    const int tid = threadIdx.x, lane = tid & 31, wid = tid >> 5;
    const int warp_m = wid & 3, warp_n = wid >> 2;
    const int row0 = blockIdx.y * 128, col0 = blockIdx.x * 128;
    const uint32_t sbase = smem_u32(hsm);
    const int quad = lane >> 3;

    float acc[2][8][4];
    #pragma unroll
    for (int a = 0; a < 2; a++)
        #pragma unroll
        for (int b = 0; b < 8; b++)
            #pragma unroll
            for (int c = 0; c < 4; c++) acc[a][b][c] = 0.0f;

    const int nch = kdim >> 5;
    h_loads(sbase, 0, Ah, Al, Bh, Bl, row0, col0, kdim, 0, tid);

    for (int c = 0; c < nch; c++) {
        if (c + 1 < nch) {
            h_loads(sbase, (c + 1) & 1, Ah, Al, Bh, Bl, row0, col0, kdim, (c + 1) * 32, tid);
            CPWAIT1();
        } else {
            CPWAIT0();
        }
        __syncthreads();
        const uint32_t sb = sbase + (uint32_t)((c & 1) * HSTAGE) * 2u;
        #pragma unroll
        for (int ks = 0; ks < 2; ks++) {
            const int k0 = ks * 16;
            uint32_t ahi[2][4], alo[2][4];
            #pragma unroll
            for (int mt = 0; mt < 2; mt++) {
                uint32_t aaddr = sb + (uint32_t)(((warp_m * 32 + mt * 16 + (lane & 15)) * HSTRIDE)
                                                 + k0 + (lane >> 4) * 8) * 2u;
                ldsm4(ahi[mt], aaddr);
                ldsm4(alo[mt], aaddr + HARR * 2u);
            }
            #pragma unroll
            for (int np = 0; np < 4; np++) {
                uint32_t bh[4], bl[4];
                uint32_t baddr = sb + 2u * HARR * 2u +
                    (uint32_t)(((warp_n * 64 + np * 16 + (quad >> 1) * 8 + (lane & 7)) * HSTRIDE)
                               + k0 + (quad & 1) * 8) * 2u;
                ldsm4(bh, baddr);
                ldsm4(bl, baddr + HARR * 2u);
                #pragma unroll
                for (int mt = 0; mt < 2; mt++)
                    #pragma unroll
                    for (int g = 0; g < 2; g++) {
                        const int nt = np * 2 + g;
                        uint32_t vh[2] = {bh[g * 2], bh[g * 2 + 1]};
                        uint32_t vl[2] = {bl[g * 2], bl[g * 2 + 1]};
                        mma_f16(acc[mt][nt], ahi[mt], vh);
                        mma_f16(acc[mt][nt], ahi[mt], vl);
                        mma_f16(acc[mt][nt], alo[mt], vh);
                    }
            }
        }
        __syncthreads();
    }

    const int tr = lane >> 2, tc = (lane & 3) * 2;
    #pragma unroll
    for (int mt = 0; mt < 2; mt++)
        #pragma unroll
        for (int h = 0; h < 2; h++) {
            int row = row0 + warp_m * 32 + mt * 16 + h * 8 + tr;
            #pragma unroll
            for (int nt = 0; nt < 8; nt++) {
                int col = col0 + warp_n * 64 + nt * 8 + tc;
                float v0 = acc[mt][nt][h * 2 + 0] + bias[col];
                float v1 = acc[mt][nt][h * 2 + 1] + bias[col + 1];
                *reinterpret_cast<float2*>(C + (size_t)row * ldc + col) = make_float2(v0, v1);
            }
        }
}

// ===========================================================================
// dist = sqr - 2 * (zh @ cbh^T), single bf16 product, fp16 output (32 MB).
#define CSTRIDE 40
#define CARR (128 * CSTRIDE)

__device__ __forceinline__ void cov_loads(uint32_t sbase, int buf,
                                          int row0, int code0, int kc, int tid)
{
    #pragma unroll
    for (int t = 0; t < 2; t++) {
        int seg = tid + t * 256;
        int rr = seg >> 2, cc = (seg & 3) * 8;
        uint32_t so = sbase + (uint32_t)(buf * 2 * CARR + rr * CSTRIDE + cc) * 2u;
        CP16(so,             g_zh  + (size_t)(row0 + rr) * DEMB + kc + cc);
        CP16(so + CARR * 2u, g_cbh + (size_t)(code0 + rr) * DEMB + kc + cc);
    }
    CPCOMMIT();
}

__global__ __launch_bounds__(256, 2) void k_cov()
{
    __shared__ __align__(16) __nv_bfloat16 sm[2][2][CARR];
    __shared__ float s_sqr[128];
    const int tid = threadIdx.x, lane = tid & 31, wid = tid >> 5;
    const int warp_m = wid & 3, warp_n = wid >> 2;
    const int row0 = blockIdx.y * 128, code0 = blockIdx.x * 128;
    const uint32_t sbase = smem_u32(&sm[0][0][0]);
    const int quad = lane >> 3;

    if (tid < 128) s_sqr[tid] = g_sqr[code0 + tid];

    float acc[2][8][4];
    #pragma unroll
    for (int a = 0; a < 2; a++)
        #pragma unroll
        for (int b = 0; b < 8; b++)
            #pragma unroll
            for (int c = 0; c < 4; c++) acc[a][b][c] = 0.0f;

    cov_loads(sbase, 0, row0, code0, 0, tid);
    const int nch = DEMB >> 5;
    for (int c = 0; c < nch; c++) {
        if (c + 1 < nch) { cov_loads(sbase, (c + 1) & 1, row0, code0, (c + 1) * 32, tid); CPWAIT1(); }
        else CPWAIT0();
        __syncthreads();
        const uint32_t sb = sbase + (uint32_t)((c & 1) * 2 * CARR) * 2u;
        #pragma unroll
        for (int ks = 0; ks < 2; ks++) {
            const int k0 = ks * 16;
            uint32_t a[2][4];
            #pragma unroll
            for (int mt = 0; mt < 2; mt++)
                ldsm4(a[mt], sb + (uint32_t)(((warp_m * 32 + mt * 16 + (lane & 15)) * CSTRIDE)
                                             + k0 + (lane >> 4) * 8) * 2u);
            #pragma unroll
            for (int np = 0; np < 4; np++) {
                uint32_t b[4];
                ldsm4(b, sb + CARR * 2u +
                      (uint32_t)(((warp_n * 64 + np * 16 + (quad >> 1) * 8 + (lane & 7)) * CSTRIDE)
                                 + k0 + (quad & 1) * 8) * 2u);
                #pragma unroll
                for (int mt = 0; mt < 2; mt++)
                    #pragma unroll
                    for (int g = 0; g < 2; g++) {
                        uint32_t vb[2] = {b[g * 2], b[g * 2 + 1]};
                        mma_bf16(acc[mt][np * 2 + g], a[mt], vb);
                    }
            }
        }
        __syncthreads();
    }

    const int tr = lane >> 2, tc = (lane & 3) * 2;
    #pragma unroll
    for (int mt = 0; mt < 2; mt++)
        #pragma unroll
        for (int h = 0; h < 2; h++) {
            int row = row0 + warp_m * 32 + mt * 16 + h * 8 + tr;
            #pragma unroll
            for (int nt = 0; nt < 8; nt++) {
                int colL = warp_n * 64 + nt * 8 + tc;
                float d0 = fmaf(-2.0f, acc[mt][nt][h * 2 + 0], s_sqr[colL]);
                float d1 = fmaf(-2.0f, acc[mt][nt][h * 2 + 1], s_sqr[colL + 1]);
                __half2 hd;
                hd.x = __float2half_rn(d0);
                hd.y = __float2half_rn(d1);
                *reinterpret_cast<__half2*>(g_dist + (size_t)row * KCB + code0 + colL) = hd;
            }
        }
}

// ===========================================================================
// Refine + fused scatter + fused gather. Block per row (256 threads).
__global__ __launch_bounds__(256) void k_refine(
    const float* __restrict__ cb, float* __restrict__ out)
{
    __shared__ float s_z[DEMB];
    __shared__ float s_wmin[8];
    __shared__ float s_wsq[8];
    __shared__ int   s_cand[64];
    __shared__ int   s_ncand;
    __shared__ unsigned long long s_best;

    const int row = blockIdx.x;
    const int t = threadIdx.x;
    const int wid = t >> 5, lane = t & 31;

    float zval = g_z[(size_t)row * DEMB + t];
    s_z[t] = zval;
    if (t == 0) { s_ncand = 0; s_best = 0xFFFFFFFFFFFFFFFFull; }

    const __half2* drow = reinterpret_cast<const __half2*>(g_dist + (size_t)row * KCB);
    __half2 p0 = drow[t];
    __half2 p1 = drow[256 + t];
    float dt[4];
    int   ci[4];
    dt[0] = __half2float(p0.x); ci[0] = 2 * t;
    dt[1] = __half2float(p0.y); ci[1] = 2 * t + 1;
    dt[2] = __half2float(p1.x); ci[2] = 512 + 2 * t;
    dt[3] = __half2float(p1.y); ci[3] = 512 + 2 * t + 1;
    float lm = fminf(fminf(dt[0], dt[1]), fminf(dt[2], dt[3]));
    #pragma unroll
    for (int o = 16; o > 0; o >>= 1) lm = fminf(lm, __shfl_xor_sync(0xffffffffu, lm, o));
    if (lane == 0) s_wmin[wid] = lm;
    __syncthreads();
    float thr = s_wmin[0];
    #pragma unroll
    for (int w = 1; w < 8; w++) thr = fminf(thr, s_wmin[w]);
    thr += MARGIN;

    #pragma unroll
    for (int i = 0; i < 4; i++) {
        if (dt[i] <= thr) {
            int idx = atomicAdd(&s_ncand, 1);
            if (idx < 64) s_cand[idx] = ci[i];
        }
    }
    __syncthreads();
    const int nc = s_ncand;

    if (nc <= 64) {
        for (int cc = wid; cc < nc; cc += 8) {
            int c = s_cand[cc];
            const float* cbr = cb + (size_t)c * DEMB;
            float dot = 0.0f;
            #pragma unroll
            for (int j = 0; j < 8; j++) dot = fmaf(s_z[lane + 32 * j], cbr[lane + 32 * j], dot);
            #pragma unroll
            for (int o = 16; o > 0; o >>= 1) dot += __shfl_xor_sync(0xffffffffu, dot, o);
            if (lane == 0) {
                float d = fmaf(-2.0f, dot, g_sqr[c]);
                unsigned u = __float_as_uint(d);
                u = (u & 0x80000000u) ? ~u : (u | 0x80000000u);
                atomicMin(&s_best, ((unsigned long long)u << 32) | (unsigned)c);
            }
        }
    } else {
        for (int c = wid; c < KCB; c += 8) {
            const float* cbr = cb + (size_t)c * DEMB;
            float dot = 0.0f;
            #pragma unroll
            for (int j = 0; j < 8; j++) dot = fmaf(s_z[lane + 32 * j], cbr[lane + 32 * j], dot);
            #pragma unroll
            for (int o = 16; o > 0; o >>= 1) dot += __shfl_xor_sync(0xffffffffu, dot, o);
            if (lane == 0) {
                float d = fmaf(-2.0f, dot, g_sqr[c]);
                unsigned u = __float_as_uint(d);
                u = (u & 0x80000000u) ? ~u : (u | 0x80000000u);
                atomicMin(&s_best, ((unsigned long long)u << 32) | (unsigned)c);
            }
        }
    }
    __syncthreads();

    unsigned long long p = s_best;
    int code = (int)(unsigned)(p & 0xFFFFFFFFull);
    unsigned ue = (unsigned)(p >> 32);
    float dmin = (ue & 0x80000000u) ? __uint_as_float(ue & 0x7FFFFFFFu)
                                    : __uint_as_float(~ue);

    // fused gather: x[row] = Y[code]
    {
        const float4* ysrc = reinterpret_cast<const float4*>(g_Y + (size_t)code * DIN);
        float4* xdst = reinterpret_cast<float4*>(out + OFF_X + (size_t)row * DIN);
        xdst[t] = ysrc[t];
    }

    // fused scatter: segment-sum z, counts, loss
    atomicAdd(&g_upd[(size_t)code * DEMB + t], zval);
    float sq = zval * zval;
    #pragma unroll
    for (int o = 16; o > 0; o >>= 1) sq += __shfl_xor_sync(0xffffffffu, sq, o);
    if (lane == 0) s_wsq[wid] = sq;
    __syncthreads();
    if (t == 0) {
        float tot = 0.0f;
        #pragma unroll
        for (int w = 0; w < 8; w++) tot += s_wsq[w];
        out[OFF_CODES + row] = (float)code;
        atomicAdd(&g_loss, tot + dmin);
        atomicAdd(&g_cnt[code], 1.0f);
    }
}

// ===========================================================================
// Fused prep: one codebook read -> sqr, bf16 cb, fp16 hi/lo cb; zero accs.
__global__ __launch_bounds__(256) void k_prep(const float* __restrict__ cb) {
    int k = blockIdx.x, t = threadIdx.x;
    float v = cb[k * DEMB + t];
    g_cbh[k * DEMB + t] = __float2bfloat16(v);
    __half h = __float2half_rn(v);
    g_cbh16[k * DEMB + t] = h;
    g_cbl16[k * DEMB + t] = __float2half_rn(v - __half2float(h));
    g_upd[k * DEMB + t] = 0.0f;

    float s = v * v;
    #pragma unroll
    for (int o = 16; o > 0; o >>= 1) s += __shfl_xor_sync(0xffffffffu, s, o);
    __shared__ float wsum[8];
    if ((t & 31) == 0) wsum[t >> 5] = s;
    __syncthreads();
    if (t == 0) {
        float tot = 0.0f;
        #pragma unroll
        for (int w = 0; w < 8; w++) tot += wsum[w];
        g_sqr[k] = tot;
        g_cnt[k] = 0.0f;
        if (k == 0) g_loss = 0.0f;
    }
}

// Coalesced tiled transpose + fp16 hi/lo split: dst[C,R] = split(src[R,C]^T).
// 32x32 tiles, 256 threads (32x8, 4 rows each). R, C multiples of 32.
__global__ __launch_bounds__(256) void k_trsplit16(
    const float* __restrict__ src, __half* __restrict__ hi,
    __half* __restrict__ lo, int R, int C)
{
    __shared__ float tile[32][33];
    const int bx = blockIdx.x * 32;   // col base in src (C dim)
    const int by = blockIdx.y * 32;   // row base in src (R dim)
    const int tx = threadIdx.x & 31, ty = threadIdx.x >> 5;   // 32 x 8

    #pragma unroll
    for (int i = 0; i < 4; i++) {
        int r = ty * 4 + i;
        tile[r][tx] = src[(size_t)(by + r) * C + bx + tx];
    }
    __syncthreads();
    #pragma unroll
    for (int i = 0; i < 4; i++) {
        int ro = ty * 4 + i;           // output row (src col)
        float v = tile[tx][ro];
        __half h = __float2half_rn(v);
        size_t o = (size_t)(bx + ro) * R + by + tx;
        hi[o] = h;
        lo[o] = __float2half_rn(v - __half2float(h));
    }
}

// ---------------------------------------------------------------------------
__global__ __launch_bounds__(1024) void k_final_small(
    const float* __restrict__ ema_size_in, float* __restrict__ out)
{
    __shared__ float sh[1024];
    int t = threadIdx.x;
    float cnt = g_cnt[t];
    float esz = ema_size_in[t] + ALPHA * (cnt - ema_size_in[t]);
    out[OFF_EMA_SIZE + t] = esz;

    sh[t] = esz;
    __syncthreads();
    for (int s = 512; s > 0; s >>= 1) {
        if (t < s) sh[t] += sh[t + s];
        __syncthreads();
    }
    float n = sh[0];
    __syncthreads();

    float coef = n / (n + (float)KCB * EPSV);
    g_size[t]  = coef * (esz + EPSV);

    float p = cnt * (1.0f / (float)NROWS);
    float e = (cnt > 0.0f) ? (-p * logf(p)) : 0.0f;
    sh[t] = e;
    __syncthreads();
    for (int s = 512; s > 0; s >>= 1) {
        if (t < s) sh[t] += sh[t + s];
        __syncthreads();
    }
    if (t == 0) {
        out[OFF_ENT]    = sh[0] / logf(2.0f);
        out[OFF_EMB]    = g_loss;
        out[OFF_COMMIT] = g_loss;
    }
}

__global__ void k_ema(const float* __restrict__ ema_vecs_in, float* __restrict__ out) {
    int i = blockIdx.x * blockDim.x + threadIdx.x;
    float v = ema_vecs_in[i] + ALPHA * (g_upd[i] - ema_vecs_in[i]);
    out[OFF_EMA_VECS + i] = v;
    out[OFF_WEIGHT + i]   = v / g_size[i >> 8];
}

// ---------------------------------------------------------------------------
extern "C" void kernel_launch(void* const* d_in, const int* in_sizes, int n_in,
                              void* d_out, int out_size) {
    const float* input    = (const float*)d_in[0];
    const float* W_send   = (const float*)d_in[1];
    const float* b_send   = (const float*)d_in[2];
    const float* W_recv   = (const float*)d_in[3];
    const float* b_recv   = (const float*)d_in[4];
    const float* codebook = (const float*)d_in[5];
    const float* ema_vecs = (const float*)d_in[6];
    const float* ema_size = (const float*)d_in[7];
    float* out = (float*)d_out;

    float *z_ptr, *Y_ptr;
    __half *wsh, *wsl, *wrh, *wrl, *cb16h, *cb16l;
    __nv_bfloat16 *zh;
    cudaGetSymbolAddress((void**)&z_ptr, g_z);
    cudaGetSymbolAddress((void**)&Y_ptr, g_Y);
    cudaGetSymbolAddress((void**)&wsh, g_wsh);   cudaGetSymbolAddress((void**)&wsl, g_wsl);
    cudaGetSymbolAddress((void**)&wrh, g_wrh);   cudaGetSymbolAddress((void**)&wrl, g_wrl);
    cudaGetSymbolAddress((void**)&cb16h, g_cbh16); cudaGetSymbolAddress((void**)&cb16l, g_cbl16);
    cudaGetSymbolAddress((void**)&zh, g_zh);

    static cudaStream_t s1 = nullptr, s2 = nullptr;
    static cudaEvent_t eFork = nullptr, ePc = nullptr, eY = nullptr, eE = nullptr;
    if (!s1) {
        cudaStreamCreateWithFlags(&s1, cudaStreamNonBlocking);
        cudaStreamCreateWithFlags(&s2, cudaStreamNonBlocking);
        cudaEventCreateWithFlags(&eFork, cudaEventDisableTiming);
        cudaEventCreateWithFlags(&ePc,   cudaEventDisableTiming);
        cudaEventCreateWithFlags(&eY,    cudaEventDisableTiming);
        cudaEventCreateWithFlags(&eE,    cudaEventDisableTiming);
        cudaFuncSetAttribute(k_zgemm, cudaFuncAttributeMaxDynamicSharedMemorySize, HSMEM_BYTES);
        cudaFuncSetAttribute(k_hgemm, cudaFuncAttributeMaxDynamicSharedMemorySize, HSMEM_BYTES);
    }

    // fork worker streams off the capture/default stream
    cudaEventRecord(eFork, 0);
    cudaStreamWaitEvent(s1, eFork, 0);
    cudaStreamWaitEvent(s2, eFork, 0);

    // s1: z chain (full grid — R15 schedule)
    k_trsplit16<<<dim3(DEMB / 32, DIN / 32), 256, 0, s1>>>(W_send, wsh, wsl, DIN, DEMB);
    k_zgemm<<<dim3(2, 128), 256, HSMEM_BYTES, s1>>>(input, wsh, wsl, b_send,
                                                    z_ptr, zh, DEMB, DIN);

    // s2: fused prep, then Y (overlaps z)
    k_prep<<<KCB, 256, 0, s2>>>(codebook);
    cudaEventRecord(ePc, s2);   // cov/refine deps ready (sqr, cbh, zeroed accs)
    k_trsplit16<<<dim3(DIN / 32, DEMB / 32), 256, 0, s2>>>(W_recv, wrh, wrl, DEMB, DIN);
    k_hgemm<<<dim3(8, 8), 256, HSMEM_BYTES, s2>>>(cb16h, cb16l, wrh, wrl, b_recv,
                                                  Y_ptr, DIN, DEMB);
    cudaEventRecord(eY, s2);

    // s1: cov -> refine (+fused scatter/gather) -> final -> ema
    cudaStreamWaitEvent(s1, ePc, 0);
    k_cov<<<dim3(8, 128), 256, 0, s1>>>();
    cudaStreamWaitEvent(s1, eY, 0);
    k_refine<<<NROWS, 256, 0, s1>>>(codebook, out);
    k_final_small<<<1, 1024, 0, s1>>>(ema_size, out);
    k_ema<<<1024, 256, 0, s1>>>(ema_vecs, out);
    cudaEventRecord(eE, s1);

    // join back to the default/capture stream
    cudaStreamWaitEvent(0, eE, 0);
}